// round 15
// baseline (speedup 1.0000x reference)
#include <cuda_runtime.h>
#include <cuda_fp16.h>
#include <cstdint>

// ============================================================================
// MLPList: B=32768 rows, 63 stacked MLPs (64->64->64->1), causal input mask.
// R13 (re-bench; previous round died to container infra, no signal):
// R12 math (fp16 1-MMA/product, half2 epilogues, MMA layer-3) with
// M=16 per warp / 64-row CTAs: regs ~120 -> 4 CTAs/SM (16 warps) to raise
// tensor-pipe overlap (util = 1-(1-d)^w model). Grid (512,4)=2048.
// ============================================================================
#define NI 63
#define DK 64
#define HN 64
#define NCHUNK 4

__device__ __align__(16) unsigned char g_wpack[NI * 16384]; // W1,W2 fp16 (8KB each)
__device__ __align__(16) uint32_t g_bpack[NI * 128];        // b1h2[32],b2h2[32],w3h2[32],b3,pad
__device__ float g_o0;

// ---------------------------------------------------------------------------
__device__ __forceinline__ uint32_t smem_u32(const void* p) {
    uint32_t a;
    asm("{ .reg .u64 t; cvta.to.shared.u64 t, %1; cvt.u32.u64 %0, t; }"
        : "=r"(a) : "l"(p));
    return a;
}

__device__ __forceinline__ uint32_t packh2(float a, float b) {
    __half2 h = __floats2half2_rn(a, b);
    return *(uint32_t*)&h;
}

// relu(fp16(a,b) + bias2) in half2, returned as packed u32
__device__ __forceinline__ uint32_t relu_bias_h2(float a, float b, uint32_t bias2) {
    __half2 v = __floats2half2_rn(a, b);
    __half2 bb = *(__half2*)&bias2;
    __half2 z = __float2half2_rn(0.f);
    __half2 r = __hmax2(__hadd2(v, bb), z);
    return *(uint32_t*)&r;
}

__device__ __forceinline__ void mma16816(float* d, const uint32_t* a, const uint32_t* b) {
    asm volatile(
        "mma.sync.aligned.m16n8k16.row.col.f32.f16.f16.f32 "
        "{%0,%1,%2,%3}, {%4,%5,%6,%7}, {%8,%9}, {%0,%1,%2,%3};"
        : "+f"(d[0]), "+f"(d[1]), "+f"(d[2]), "+f"(d[3])
        : "r"(a[0]), "r"(a[1]), "r"(a[2]), "r"(a[3]), "r"(b[0]), "r"(b[1]));
}

__device__ __forceinline__ void ldsm4(uint32_t& r0, uint32_t& r1, uint32_t& r2,
                                      uint32_t& r3, uint32_t addr) {
    asm volatile("ldmatrix.sync.aligned.m8n8.x4.shared.b16 {%0,%1,%2,%3}, [%4];"
                 : "=r"(r0), "=r"(r1), "=r"(r2), "=r"(r3) : "r"(addr));
}

// ============================================================================
// Prep kernels
// ============================================================================
__global__ void prep_weights_kernel(const float* __restrict__ W1,
                                    const float* __restrict__ W2) {
    int idx = blockIdx.x * blockDim.x + threadIdx.x;
    if (idx >= NI * DK * HN) return;
    int i = idx >> 12;
    int n = (idx >> 6) & 63;
    int k = idx & 63;
    uint32_t off = (uint32_t)(n * 128) + (uint32_t)((k * 2) ^ ((n & 7) << 4));
    unsigned char* base = g_wpack + (size_t)i * 16384;

    float v1 = (k <= i) ? W1[((size_t)i * DK + k) * HN + n] : 0.0f;
    *(__half*)(base + 0 * 8192 + off) = __float2half_rn(v1);

    float v2 = W2[((size_t)i * HN + k) * HN + n];
    *(__half*)(base + 1 * 8192 + off) = __float2half_rn(v2);
}

__global__ void prep_bias_kernel(const float* __restrict__ b1, const float* __restrict__ b2,
                                 const float* __restrict__ W3, const float* __restrict__ b3) {
    int idx = blockIdx.x * blockDim.x + threadIdx.x;
    if (idx >= NI * 128) return;
    int i = idx >> 7, t = idx & 127;
    uint32_t v = 0;
    if (t < 32)       v = packh2(b1[i * 64 + 2 * t],        b1[i * 64 + 2 * t + 1]);
    else if (t < 64)  v = packh2(b2[i * 64 + 2 * (t - 32)], b2[i * 64 + 2 * (t - 32) + 1]);
    else if (t < 96)  v = packh2(W3[i * 64 + 2 * (t - 64)], W3[i * 64 + 2 * (t - 64) + 1]);
    else if (t == 96) v = __float_as_uint(b3[i]);
    g_bpack[i * 128 + t] = v;
}

__global__ void prep_dim0_kernel(const float* __restrict__ w01, const float* __restrict__ b01,
                                 const float* __restrict__ w02, const float* __restrict__ b02,
                                 const float* __restrict__ w03, const float* __restrict__ b03) {
    __shared__ float h0s[64];
    __shared__ float ps[64];
    int h = threadIdx.x;
    float a = b01[h];
#pragma unroll
    for (int t = 0; t < 10; t++) {
        float v = 0.1f * (-5.0f + (float)t * (10.0f / 9.0f));
        a = fmaf(v, w01[t * 64 + h], a);
    }
    h0s[h] = fmaxf(a, 0.0f);
    __syncthreads();
    float a2 = b02[h];
#pragma unroll
    for (int k = 0; k < 64; k++) a2 = fmaf(h0s[k], w02[k * 64 + h], a2);
    ps[h] = fmaxf(a2, 0.0f) * w03[h];
    __syncthreads();
    if (h == 0) {
        float s = b03[0];
        for (int k = 0; k < 64; k++) s += ps[k];
        g_o0 = s;
    }
}

// ============================================================================
// Main kernel
// ============================================================================
constexpr int OFF_X    = 0;              // 64x64 fp16 X tile (8KB, swizzled)
constexpr int OFF_W    = 8192;           // 2 x 16384B (W1, W2)
constexpr int OFF_BIAS = 40960;          // 2 x 512B
constexpr int SMEM_BYTES = 41984;

__device__ __forceinline__ void stage_i(char* smem, int i, int buf, int tid) {
    const unsigned char* src = g_wpack + (size_t)i * 16384;
    uint32_t dst = smem_u32(smem + OFF_W + buf * 16384);
#pragma unroll
    for (int j = 0; j < 8; j++) {
        int c = tid + j * 128;   // 1024 chunks of 16B = 16KB
        asm volatile("cp.async.cg.shared.global [%0], [%1], 16;"
                     :: "r"(dst + c * 16), "l"(src + (size_t)c * 16));
    }
    if (tid < 32) {
        const unsigned char* bsrc = (const unsigned char*)(g_bpack + (size_t)i * 128);
        uint32_t bdst = smem_u32(smem + OFF_BIAS + buf * 512) + tid * 16;
        asm volatile("cp.async.cg.shared.global [%0], [%1], 16;"
                     :: "r"(bdst), "l"(bsrc + tid * 16));
    }
    asm volatile("cp.async.commit_group;" ::: "memory");
}

__global__ void __launch_bounds__(128, 4)
mlplist_main_kernel(const float* __restrict__ x, float* __restrict__ out, int B) {
    extern __shared__ char smem[];
    const int tid  = threadIdx.x;
    const int warp = tid >> 5, lane = tid & 31;
    const int tig  = lane & 3, grp = lane >> 2;
    const int q    = lane >> 3, r = lane & 7;    // ldmatrix lane decomposition
    const int rowBase = blockIdx.x * 64;          // 64-row CTA tile
    const int chunk = blockIdx.y;
    const int niters = (NI - chunk + NCHUNK - 1) / NCHUNK;   // 16,16,16,15
    const float o0 = g_o0;

    // ---- ldmatrix per-lane address constants ----
    const uint32_t xbase = smem_u32(smem + OFF_X);
    const int arow = warp * 16 + (q & 1) * 8 + r;
    const uint32_t aBase = xbase + (uint32_t)(arow * 128);
    const uint32_t aLow = (uint32_t)(((q >> 1) * 16) ^ (r << 4));
    uint32_t bRowOff[4];
#pragma unroll
    for (int g = 0; g < 4; g++)
        bRowOff[g] = (uint32_t)((16 * g + (q >> 1) * 8 + r) * 128);
    const uint32_t bLow = (uint32_t)(((q & 1) * 16) ^ (r << 4));

    // ---- load X tile -> fp16 swizzled tile (2 threads per row) ----
    {
        const int row = rowBase + (tid >> 1);
        const int half = tid & 1;
        if (row < B) {
            const float4* xr = (const float4*)(x + (size_t)row * DK + half * 32);
#pragma unroll
            for (int c = 0; c < 4; c++) {
                float4 f0 = xr[2 * c], f1 = xr[2 * c + 1];
                uint4 hp;
                hp.x = packh2(f0.x, f0.y);
                hp.y = packh2(f0.z, f0.w);
                hp.z = packh2(f1.x, f1.y);
                hp.w = packh2(f1.z, f1.w);
                int lrow = tid >> 1;
                uint32_t off = (uint32_t)(lrow * 128)
                             + (uint32_t)((half * 64 + c * 16) ^ ((lrow & 7) << 4));
                *(uint4*)(smem + OFF_X + off) = hp;
            }
        }
    }

    stage_i(smem, chunk, 0, tid);

    for (int t = 0; t < niters; t++) {
        const int i = chunk + t * NCHUNK;
        const int buf = t & 1;
        __syncthreads();
        if (t + 1 < niters) {
            stage_i(smem, i + NCHUNK, buf ^ 1, tid);
            asm volatile("cp.async.wait_group 1;" ::: "memory");
        } else {
            asm volatile("cp.async.wait_group 0;" ::: "memory");
        }
        __syncthreads();

        const uint32_t wb1 = smem_u32(smem + OFF_W + buf * 16384);      // W1
        const uint32_t wb2 = wb1 + 8192;                                 // W2
        const uint32_t* bias_u = (const uint32_t*)(smem + OFF_BIAS + buf * 512);
        const uint32_t* b1h2 = bias_u;          // 32 half2
        const uint32_t* b2h2 = bias_u + 32;
        const uint32_t* w3h2 = bias_u + 64;
        const float b3v = __uint_as_float(bias_u[96]);

        // w3 B-fragment per k-step (n=0 column only -> grp==0 lanes hold data)
        uint32_t w3b[4][2];
#pragma unroll
        for (int kk = 0; kk < 4; kk++) {
            w3b[kk][0] = (grp == 0) ? w3h2[kk * 8 + tig]     : 0u;
            w3b[kk][1] = (grp == 0) ? w3h2[kk * 8 + 4 + tig] : 0u;
        }

        float acc[8][4];
#pragma unroll
        for (int j = 0; j < 8; j++)
#pragma unroll
            for (int rr = 0; rr < 4; rr++) acc[j][rr] = 0.0f;

        // ---- Layer 1: acc += X_fp16 @ W1_fp16^T (masked K chunks skipped) ----
        const int kt1 = (i >> 4) + 1;
        for (int kt = 0; kt < kt1; kt++) {
            const uint32_t kb = (uint32_t)(kt * 32);
            const uint32_t ao = aLow ^ kb;
            const uint32_t bo = bLow ^ kb;
            uint32_t aF[4];
            ldsm4(aF[0], aF[1], aF[2], aF[3], aBase + ao);
            uint32_t bF[8][2];
#pragma unroll
            for (int g = 0; g < 4; g++)
                ldsm4(bF[2 * g][0], bF[2 * g][1], bF[2 * g + 1][0], bF[2 * g + 1][1],
                      wb1 + bRowOff[g] + bo);
#pragma unroll
            for (int j = 0; j < 8; j++)
                mma16816(acc[j], aF, bF[j]);
        }

        // ---- bias + relu (half2) -> fp16 layer-2 A fragments ----
        uint32_t A2[4][4];
#pragma unroll
        for (int k2 = 0; k2 < 4; k2++) {
            const int j0 = 2 * k2, j1 = 2 * k2 + 1;
            const uint32_t bb0 = b1h2[j0 * 4 + tig];
            const uint32_t bb1 = b1h2[j1 * 4 + tig];
            A2[k2][0] = relu_bias_h2(acc[j0][0], acc[j0][1], bb0);
            A2[k2][1] = relu_bias_h2(acc[j0][2], acc[j0][3], bb0);
            A2[k2][2] = relu_bias_h2(acc[j1][0], acc[j1][1], bb1);
            A2[k2][3] = relu_bias_h2(acc[j1][2], acc[j1][3], bb1);
        }

        // ---- Layer 2 ----
#pragma unroll
        for (int j = 0; j < 8; j++)
#pragma unroll
            for (int rr = 0; rr < 4; rr++) acc[j][rr] = 0.0f;

#pragma unroll
        for (int k2 = 0; k2 < 4; k2++) {
            const uint32_t bo = bLow ^ (uint32_t)(k2 * 32);
            uint32_t bF[8][2];
#pragma unroll
            for (int g = 0; g < 4; g++)
                ldsm4(bF[2 * g][0], bF[2 * g][1], bF[2 * g + 1][0], bF[2 * g + 1][1],
                      wb2 + bRowOff[g] + bo);
#pragma unroll
            for (int j = 0; j < 8; j++)
                mma16816(acc[j], A2[k2], bF[j]);
        }

        // ---- Layer 3: bias+relu (half2) -> A3 fragments -> MMA with w3 ----
        {
            uint32_t A3[4][4];
#pragma unroll
            for (int kk = 0; kk < 4; kk++) {
                const int j0 = 2 * kk, j1 = 2 * kk + 1;
                const uint32_t bb0 = b2h2[j0 * 4 + tig];
                const uint32_t bb1 = b2h2[j1 * 4 + tig];
                A3[kk][0] = relu_bias_h2(acc[j0][0], acc[j0][1], bb0);
                A3[kk][1] = relu_bias_h2(acc[j0][2], acc[j0][3], bb0);
                A3[kk][2] = relu_bias_h2(acc[j1][0], acc[j1][1], bb1);
                A3[kk][3] = relu_bias_h2(acc[j1][2], acc[j1][3], bb1);
            }
            float d3[4] = {0.f, 0.f, 0.f, 0.f};
#pragma unroll
            for (int kk = 0; kk < 4; kk++)
                mma16816(d3, A3[kk], w3b[kk]);
            // D col 0 lives on tig==0 lanes: d3[0]=row grp, d3[2]=row grp+8
            if (tig == 0) {
                const int row = rowBase + warp * 16 + grp;
                if (row < B)     out[(size_t)row * 64 + (i + 1)]       = d3[0] + b3v;
                if (row + 8 < B) out[(size_t)(row + 8) * 64 + (i + 1)] = d3[2] + b3v;
            }
        }
    }

    // dim-0 column (batch-constant), written by chunk-0 CTAs only
    if (chunk == 0 && tid < 64 && rowBase + tid < B)
        out[(size_t)(rowBase + tid) * 64] = o0;
}

// ============================================================================
// Launch
// ============================================================================
extern "C" void kernel_launch(void* const* d_in, const int* in_sizes, int n_in,
                              void* d_out, int out_size) {
    const float* x   = (const float*)d_in[0];
    const float* W1  = (const float*)d_in[1];
    const float* b1  = (const float*)d_in[2];
    const float* W2  = (const float*)d_in[3];
    const float* b2  = (const float*)d_in[4];
    const float* W3  = (const float*)d_in[5];
    const float* b3  = (const float*)d_in[6];
    const float* w01 = (const float*)d_in[7];
    const float* b01 = (const float*)d_in[8];
    const float* w02 = (const float*)d_in[9];
    const float* b02 = (const float*)d_in[10];
    const float* w03 = (const float*)d_in[11];
    const float* b03 = (const float*)d_in[12];
    float* out = (float*)d_out;

    const int B = in_sizes[0] / DK;

    prep_weights_kernel<<<(NI * DK * HN + 255) / 256, 256>>>(W1, W2);
    prep_bias_kernel<<<(NI * 128 + 255) / 256, 256>>>(b1, b2, W3, b3);
    prep_dim0_kernel<<<1, 64>>>(w01, b01, w02, b02, w03, b03);

    static bool attr_set = false;
    if (!attr_set) {
        cudaFuncSetAttribute(mlplist_main_kernel,
                             cudaFuncAttributeMaxDynamicSharedMemorySize, SMEM_BYTES);
        attr_set = true;
    }
    dim3 grid((B + 63) / 64, NCHUNK);
    mlplist_main_kernel<<<grid, 128, SMEM_BYTES>>>(x, out, B);
}